// round 15
// baseline (speedup 1.0000x reference)
#include <cuda_runtime.h>
#include <cuda_bf16.h>
#include <cstdint>

// Fixed problem shapes
#define B_  1
#define E_  128
#define L_  256
#define H_  12
#define DH_ 64
#define D_  768          // H_*DH_
#define D3_ 2304         // 3*D_
#define N_  32768        // B_*E_*L_
#define EPSLN 1e-5f
#define NEGV  -10000.0f

// Scratch (allocations forbidden -> device globals)
__device__ float g_qkv[(size_t)N_ * D3_];            // 302 MB; aliased as 2x bf16 [N,D3]
__device__ float g_tmp[(size_t)N_ * D_];             // 100 MB
__device__ __nv_bfloat16 g_ah[(size_t)N_ * D_];
__device__ __nv_bfloat16 g_al[(size_t)N_ * D_];
__device__ __nv_bfloat16 g_wrh[(size_t)D3_ * D_];
__device__ __nv_bfloat16 g_wrl[(size_t)D3_ * D_];
__device__ __nv_bfloat16 g_wch[(size_t)D3_ * D_];
__device__ __nv_bfloat16 g_wcl[(size_t)D3_ * D_];

// ---------------------------------------------------------------------------
// arch-agnostic PTX helpers
// ---------------------------------------------------------------------------
__device__ __forceinline__ uint32_t smem_u32(const void* p) {
    uint32_t a;
    asm("{ .reg .u64 t; cvta.to.shared.u64 t, %1; cvt.u32.u64 %0, t; }" : "=r"(a) : "l"(p));
    return a;
}
__device__ __forceinline__ void cp16(uint32_t s, const void* g) {
    asm volatile("cp.async.cg.shared.global [%0], [%1], 16;" :: "r"(s), "l"(g) : "memory");
}
__device__ __forceinline__ void cp_commit() {
    asm volatile("cp.async.commit_group;" ::: "memory");
}
template <int N>
__device__ __forceinline__ void cp_wait() {
    asm volatile("cp.async.wait_group %0;" :: "n"(N) : "memory");
}
__device__ __forceinline__ void ldsm4(uint32_t* r, uint32_t a) {
    asm volatile("ldmatrix.sync.aligned.m8n8.x4.shared.b16 {%0,%1,%2,%3}, [%4];"
                 : "=r"(r[0]), "=r"(r[1]), "=r"(r[2]), "=r"(r[3]) : "r"(a));
}
__device__ __forceinline__ void ldsm2t(uint32_t* r, uint32_t a) {
    asm volatile("ldmatrix.sync.aligned.m8n8.x2.trans.shared.b16 {%0,%1}, [%2];"
                 : "=r"(r[0]), "=r"(r[1]) : "r"(a));
}
__device__ __forceinline__ void mma16816(float* d, const uint32_t* a, const uint32_t* b) {
    asm volatile(
        "mma.sync.aligned.m16n8k16.row.col.f32.bf16.bf16.f32 "
        "{%0,%1,%2,%3}, {%4,%5,%6,%7}, {%8,%9}, {%0,%1,%2,%3};"
        : "+f"(d[0]), "+f"(d[1]), "+f"(d[2]), "+f"(d[3])
        : "r"(a[0]), "r"(a[1]), "r"(a[2]), "r"(a[3]), "r"(b[0]), "r"(b[1]));
}
__device__ __forceinline__ uint32_t pack2(__nv_bfloat16 a, __nv_bfloat16 b) {
    __nv_bfloat162 t = __halves2bfloat162(a, b);
    return *reinterpret_cast<uint32_t*>(&t);
}
__device__ __forceinline__ uint32_t sw128(uint32_t off) {
    return off ^ ((off >> 3) & 0x70);
}

// ---------------------------------------------------------------------------
// split: fp32 -> bf16 hi + bf16 lo
// ---------------------------------------------------------------------------
__global__ __launch_bounds__(256) void split_f32(
    const float* __restrict__ in, __nv_bfloat16* __restrict__ hi,
    __nv_bfloat16* __restrict__ lo, int n)
{
    int i = (blockIdx.x * 256 + threadIdx.x) * 4;
    if (i >= n) return;
    float4 v = *(const float4*)(in + i);
    float f[4] = {v.x, v.y, v.z, v.w};
    __nv_bfloat16 h[4], l[4];
#pragma unroll
    for (int q = 0; q < 4; q++) {
        h[q] = __float2bfloat16(f[q]);
        l[q] = __float2bfloat16(f[q] - __bfloat162float(h[q]));
    }
    *(__nv_bfloat162*)(hi + i)     = __halves2bfloat162(h[0], h[1]);
    *(__nv_bfloat162*)(hi + i + 2) = __halves2bfloat162(h[2], h[3]);
    *(__nv_bfloat162*)(lo + i)     = __halves2bfloat162(l[0], l[1]);
    *(__nv_bfloat162*)(lo + i + 2) = __halves2bfloat162(l[2], l[3]);
}

// ---------------------------------------------------------------------------
// bf16 3-way-split GEMM via mma.sync. Epilogue: SMEM restage -> STG.128.
// ---------------------------------------------------------------------------
#define GK 768
#define GM 2304
#define BKC 32
#define NIT 24
#define ABUF_B 16384
#define STG_B  (2 * ABUF_B)
#define SMEM_GEMM (3 * STG_B + 1024)
#define EROW 272                     // epilogue smem row stride (bytes)

__device__ __forceinline__ void issue_stage3(
    uint32_t sbase, int kc,
    const __nv_bfloat16* __restrict__ pAh, const __nv_bfloat16* __restrict__ pAl,
    const __nv_bfloat16* __restrict__ pBh, const __nv_bfloat16* __restrict__ pBl,
    int tid)
{
#pragma unroll
    for (int i = 0; i < 4; i++) {
        int idx = i * 256 + tid;
        int r = idx >> 3, half = (idx >> 2) & 1, c16 = idx & 3;
        const __nv_bfloat16* g = (half ? pAl : pAh) + (size_t)r * GK + kc + c16 * 8;
        uint32_t off = (uint32_t)(r * 128 + half * 64 + c16 * 16);
        cp16(sbase + sw128(off), g);
    }
#pragma unroll
    for (int i = 0; i < 4; i++) {
        int idx = i * 256 + tid;
        int r = idx >> 3, half = (idx >> 2) & 1, c16 = idx & 3;
        const __nv_bfloat16* g = (half ? pBl : pBh) + (size_t)r * GK + kc + c16 * 8;
        uint32_t off = (uint32_t)(r * 128 + half * 64 + c16 * 16);
        cp16(sbase + ABUF_B + sw128(off), g);
    }
    cp_commit();
}

__global__ __launch_bounds__(256, 2) void gemm_hmma_x3(
    const __nv_bfloat16* __restrict__ Ah, const __nv_bfloat16* __restrict__ Al,
    const __nv_bfloat16* __restrict__ Bh, const __nv_bfloat16* __restrict__ Bl,
    const float* __restrict__ bias,
    __nv_bfloat16* __restrict__ Ch, __nv_bfloat16* __restrict__ Cl)
{
    extern __shared__ char dynsm[];
    uint32_t smb = smem_u32(dynsm);
    smb = (smb + 1023u) & ~1023u;

    const int tid  = threadIdx.x;
    const int wid  = tid >> 5, lane = tid & 31;
    const int wm   = wid >> 2;
    const int wn   = wid & 3;
    const int tileN = blockIdx.x;
    const int tileM = blockIdx.y;

    const __nv_bfloat16* pA0 = Ah + (size_t)tileM * 128 * GK;
    const __nv_bfloat16* pA1 = Al + (size_t)tileM * 128 * GK;
    const __nv_bfloat16* pB0 = Bh + (size_t)tileN * 128 * GK;
    const __nv_bfloat16* pB1 = Bl + (size_t)tileN * 128 * GK;

    issue_stage3(smb + 0 * STG_B, 0 * BKC, pA0, pA1, pB0, pB1, tid);
    issue_stage3(smb + 1 * STG_B, 1 * BKC, pA0, pA1, pB0, pB1, tid);

    float acc[4][4][4];
#pragma unroll
    for (int a = 0; a < 4; a++)
#pragma unroll
        for (int b = 0; b < 4; b++)
#pragma unroll
            for (int c = 0; c < 4; c++) acc[a][b][c] = 0.f;

    const int aRow  = lane & 15;
    const int aColB = (lane >> 4) * 16;
    const int grp   = lane >> 3;
    const int bRow  = ((grp >> 1) * 8) + (lane & 7);
    const int bColB = (grp & 1) * 16;

    int st = 0;
    for (int it = 0; it < NIT; it++) {
        if (it < NIT - 2) cp_wait<1>(); else cp_wait<0>();
        __syncthreads();

        if (it + 2 < NIT) {
            int stn = st + 2; if (stn >= 3) stn -= 3;
            issue_stage3(smb + (uint32_t)stn * STG_B, (it + 2) * BKC,
                         pA0, pA1, pB0, pB1, tid);
        }

        const uint32_t sA = smb + (uint32_t)st * STG_B;
        const uint32_t sB = sA + ABUF_B;

#pragma unroll
        for (int ks = 0; ks < 2; ks++) {
            const int kb = ks * 32;
            uint32_t ah[4][4], al4[4][4], bh4[2][4], bl4[2][4];
#pragma unroll
            for (int mt = 0; mt < 4; mt++) {
                uint32_t off = (uint32_t)((wm * 64 + mt * 16 + aRow) * 128 + kb + aColB);
                ldsm4(ah[mt],  sA + sw128(off));
                ldsm4(al4[mt], sA + sw128(off + 64));
            }
#pragma unroll
            for (int pr = 0; pr < 2; pr++) {
                uint32_t off = (uint32_t)((wn * 32 + pr * 16 + bRow) * 128 + kb + bColB);
                ldsm4(bh4[pr], sB + sw128(off));
                ldsm4(bl4[pr], sB + sw128(off + 64));
            }
#pragma unroll
            for (int mt = 0; mt < 4; mt++)
#pragma unroll
                for (int pr = 0; pr < 2; pr++)
#pragma unroll
                    for (int half = 0; half < 2; half++) {
                        const int nt = pr * 2 + half;
                        mma16816(acc[mt][nt], ah[mt],  &bh4[pr][half * 2]);
                        mma16816(acc[mt][nt], ah[mt],  &bl4[pr][half * 2]);
                        mma16816(acc[mt][nt], al4[mt], &bh4[pr][half * 2]);
                    }
        }
        st++; if (st == 3) st = 0;
    }

    // ---- epilogue: split to hi/lo, restage via SMEM, coalesced STG.128 ----
    __syncthreads();                          // mainloop done with stage smem
    const uint32_t eHi = smb;                 // 128 x EROW bytes
    const uint32_t eLo = smb + 128 * EROW;    // 128 x EROW bytes (total ~68KB)

    const int r0 = wm * 64 + (lane >> 2);
    const int c0 = wn * 32 + (lane & 3) * 2;
#pragma unroll
    for (int mt = 0; mt < 4; mt++) {
#pragma unroll
        for (int nt = 0; nt < 4; nt++) {
            const int col  = c0 + nt * 8;
            const int gcol = tileN * 128 + col;
            const float b0 = bias[gcol], b1 = bias[gcol + 1];
#pragma unroll
            for (int rr = 0; rr < 2; rr++) {
                const int row = r0 + mt * 16 + rr * 8;
                float y0 = acc[mt][nt][rr * 2 + 0] + b0;
                float y1 = acc[mt][nt][rr * 2 + 1] + b1;
                __nv_bfloat16 h0 = __float2bfloat16(y0);
                __nv_bfloat16 h1 = __float2bfloat16(y1);
                __nv_bfloat16 l0 = __float2bfloat16(y0 - __bfloat162float(h0));
                __nv_bfloat16 l1 = __float2bfloat16(y1 - __bfloat162float(h1));
                uint32_t off = (uint32_t)(row * EROW + col * 2);
                *(uint32_t*)(dynsm + (eHi - smem_u32(dynsm)) + off) = pack2(h0, h1);
                *(uint32_t*)(dynsm + (eLo - smem_u32(dynsm)) + off) = pack2(l0, l1);
            }
        }
    }
    __syncthreads();

    // stream out: 128 rows x 16 chunks(16B) per array; 8 chunks/thread/array
#pragma unroll
    for (int t = 0; t < 8; t++) {
        int idx = t * 256 + tid;              // 0..2047
        int r = idx >> 4, c = idx & 15;
        size_t gp = (size_t)(tileM * 128 + r) * GM + tileN * 128 + c * 8;
        uint4 vh = *(uint4*)(dynsm + (eHi - smem_u32(dynsm)) + r * EROW + c * 16);
        uint4 vl = *(uint4*)(dynsm + (eLo - smem_u32(dynsm)) + r * EROW + c * 16);
        *(uint4*)(Ch + gp) = vh;
        *(uint4*)(Cl + gp) = vl;
    }
}

// ---------------------------------------------------------------------------
// Flash-style HMMA attention, bf16 hi/lo qkv inputs.
// ---------------------------------------------------------------------------
#define CH_TILE 8192
#define CH_STG  (4 * CH_TILE)

template <int MT>
__global__ __launch_bounds__(256, 1) void attn_mma(
    const __nv_bfloat16* __restrict__ qh, const __nv_bfloat16* __restrict__ ql,
    const int* __restrict__ mask, float* __restrict__ out, int colmode)
{
    constexpr int NQ  = MT * 128;
    constexpr int NCH = MT * 2;
    extern __shared__ __align__(128) char smraw[];
    const uint32_t uQh = smem_u32(smraw);
    const uint32_t uQl = uQh + NQ * 128;
    const uint32_t uST = uQl + NQ * 128;
    float* negs = (float*)(smraw + 2 * NQ * 128 + 3 * CH_STG);

    const int tid  = threadIdx.x;
    const int wid  = tid >> 5, lane = tid & 31;
    const int h    = blockIdx.x;
    const int base = colmode ? (int)blockIdx.y : (int)blockIdx.y * 256;
    const int step = colmode ? 256 : 1;

#pragma unroll
    for (int i = 0; i < NQ / 16; i++) {
        int idx = i * 256 + tid;
        int t = (idx >= NQ * 8);
        int r = (idx >> 3) & (NQ - 1);
        int c = idx & 7;
        const __nv_bfloat16* src = (t ? ql : qh) + (size_t)(base + r * step) * D3_ + h * 64 + c * 8;
        cp16((t ? uQl : uQh) + sw128((uint32_t)(r * 128 + c * 16)), src);
    }
    cp_commit();
    for (int i = tid; i < NQ; i += 256)
        negs[i] = mask[base + i * step] ? NEGV : 0.f;

    auto issue_ch = [&](int ch) {
        uint32_t sb = uST + (uint32_t)(ch % 3) * CH_STG;
#pragma unroll
        for (int i = 0; i < 8; i++) {
            int idx = i * 256 + tid;
            int tile = idx >> 9;
            int r = (idx >> 3) & 63;
            int c = idx & 7;
            const __nv_bfloat16* bp = (tile & 1) ? ql : qh;
            int coff = (tile >= 2) ? 1536 : 768;
            const __nv_bfloat16* src = bp + (size_t)(base + (ch * 64 + r) * step) * D3_
                                       + coff + h * 64 + c * 8;
            cp16(sb + (uint32_t)tile * CH_TILE + sw128((uint32_t)(r * 128 + c * 16)), src);
        }
        cp_commit();
    };
    issue_ch(0);
    if (NCH > 1) issue_ch(1);

    float s[MT][8][4], o[MT][8][4], mrow[MT][2], lrow[MT][2];
#pragma unroll
    for (int mt = 0; mt < MT; mt++) {
        mrow[mt][0] = mrow[mt][1] = -1e30f;
        lrow[mt][0] = lrow[mt][1] = 0.f;
#pragma unroll
        for (int nt = 0; nt < 8; nt++)
#pragma unroll
            for (int c = 0; c < 4; c++) o[mt][nt][c] = 0.f;
    }

    const int aRow  = lane & 15;
    const int aColB = (lane >> 4) * 16;
    const int grp   = lane >> 3;
    const int bRow4 = ((grp >> 1) * 8) + (lane & 7);
    const int bColB4 = (grp & 1) * 16;

    for (int ch = 0; ch < NCH; ch++) {
        if (ch < NCH - 1) cp_wait<1>(); else cp_wait<0>();
        __syncthreads();
        if (ch + 2 < NCH) issue_ch(ch + 2);

        const uint32_t sK = uST + (uint32_t)(ch % 3) * CH_STG;

#pragma unroll
        for (int mt = 0; mt < MT; mt++)
#pragma unroll
            for (int nt = 0; nt < 8; nt++)
#pragma unroll
                for (int c = 0; c < 4; c++) s[mt][nt][c] = 0.f;

#pragma unroll
        for (int kq = 0; kq < 4; kq++) {
            uint32_t ah[MT][4], al[MT][4];
#pragma unroll
            for (int mt = 0; mt < MT; mt++) {
                uint32_t off = (uint32_t)((wid * (MT * 16) + mt * 16 + aRow) * 128
                                          + kq * 32 + aColB);
                ldsm4(ah[mt], uQh + sw128(off));
                ldsm4(al[mt], uQl + sw128(off));
            }
            uint32_t kh4[4][4], kl4[4][4];
#pragma unroll
            for (int pr = 0; pr < 4; pr++) {
                uint32_t off = (uint32_t)((pr * 16 + bRow4) * 128 + kq * 32 + bColB4);
                ldsm4(kh4[pr], sK + sw128(off));
                ldsm4(kl4[pr], sK + CH_TILE + sw128(off));
            }
#pragma unroll
            for (int mt = 0; mt < MT; mt++)
#pragma unroll
                for (int pr = 0; pr < 4; pr++)
#pragma unroll
                    for (int half = 0; half < 2; half++) {
                        const int nt = pr * 2 + half;
                        mma16816(s[mt][nt], ah[mt], &kh4[pr][half * 2]);
                        mma16816(s[mt][nt], ah[mt], &kl4[pr][half * 2]);
                        mma16816(s[mt][nt], al[mt], &kh4[pr][half * 2]);
                    }
        }

#pragma unroll
        for (int nt = 0; nt < 8; nt++) {
            int j = ch * 64 + nt * 8 + (lane & 3) * 2;
            float n0 = negs[j], n1 = negs[j + 1];
#pragma unroll
            for (int mt = 0; mt < MT; mt++) {
                s[mt][nt][0] = s[mt][nt][0] * 0.125f + n0;
                s[mt][nt][1] = s[mt][nt][1] * 0.125f + n1;
                s[mt][nt][2] = s[mt][nt][2] * 0.125f + n0;
                s[mt][nt][3] = s[mt][nt][3] * 0.125f + n1;
            }
        }
#pragma unroll
        for (int mt = 0; mt < MT; mt++) {
#pragma unroll
            for (int hf = 0; hf < 2; hf++) {
                float rm = -1e30f;
#pragma unroll
                for (int nt = 0; nt < 8; nt++)
                    rm = fmaxf(rm, fmaxf(s[mt][nt][2 * hf], s[mt][nt][2 * hf + 1]));
                rm = fmaxf(rm, __shfl_xor_sync(0xffffffffu, rm, 1));
                rm = fmaxf(rm, __shfl_xor_sync(0xffffffffu, rm, 2));
                float mo = mrow[mt][hf];
                float mn = fmaxf(mo, rm);
                float corr = __expf(mo - mn);
                float rs = 0.f;
#pragma unroll
                for (int nt = 0; nt < 8; nt++) {
                    float p0 = __expf(s[mt][nt][2 * hf]     - mn);
                    float p1 = __expf(s[mt][nt][2 * hf + 1] - mn);
                    s[mt][nt][2 * hf] = p0; s[mt][nt][2 * hf + 1] = p1;
                    rs += p0 + p1;
                    o[mt][nt][2 * hf] *= corr; o[mt][nt][2 * hf + 1] *= corr;
                }
                rs += __shfl_xor_sync(0xffffffffu, rs, 1);
                rs += __shfl_xor_sync(0xffffffffu, rs, 2);
                lrow[mt][hf] = lrow[mt][hf] * corr + rs;
                mrow[mt][hf] = mn;
            }
        }

#pragma unroll
        for (int kk = 0; kk < 4; kk++) {
            uint32_t pah[MT][4], pal[MT][4];
#pragma unroll
            for (int mt = 0; mt < MT; mt++) {
#pragma unroll
                for (int q = 0; q < 4; q++) {
                    int nt = kk * 2 + (q >> 1);
                    int i0 = (q & 1) * 2;
                    float p0 = s[mt][nt][i0], p1 = s[mt][nt][i0 + 1];
                    __nv_bfloat16 h0 = __float2bfloat16(p0);
                    __nv_bfloat16 h1 = __float2bfloat16(p1);
                    pah[mt][q] = pack2(h0, h1);
                    __nv_bfloat16 l0 = __float2bfloat16(p0 - __bfloat162float(h0));
                    __nv_bfloat16 l1 = __float2bfloat16(p1 - __bfloat162float(h1));
                    pal[mt][q] = pack2(l0, l1);
                }
            }
#pragma unroll
            for (int nt = 0; nt < 8; nt++) {
                uint32_t vbh[2], vbl[2];
                uint32_t voff = sw128((uint32_t)((kk * 16 + (lane & 15)) * 128 + nt * 16));
                ldsm2t(vbh, sK + 2 * CH_TILE + voff);
                ldsm2t(vbl, sK + 3 * CH_TILE + voff);
#pragma unroll
                for (int mt = 0; mt < MT; mt++) {
                    mma16816(o[mt][nt], pah[mt], vbh);
                    mma16816(o[mt][nt], pah[mt], vbl);
                    mma16816(o[mt][nt], pal[mt], vbh);
                }
            }
        }
    }

#pragma unroll
    for (int mt = 0; mt < MT; mt++) {
#pragma unroll
        for (int hf = 0; hf < 2; hf++) {
            float inv = 1.f / lrow[mt][hf];
            int qrow = wid * (MT * 16) + mt * 16 + hf * 8 + (lane >> 2);
            size_t ob = (size_t)(base + qrow * step) * D_ + h * 64 + (lane & 3) * 2;
#pragma unroll
            for (int nt = 0; nt < 8; nt++) {
                float2 v = {o[mt][nt][2 * hf] * inv, o[mt][nt][2 * hf + 1] * inv};
                *(float2*)(out + ob + nt * 8) = v;
            }
        }
    }
}

#define SMEM_ATT_ROW (2 * 256 * 128 + 3 * CH_STG + 256 * 4)
#define SMEM_ATT_COL (2 * 128 * 128 + 3 * CH_STG + 128 * 4)

// ---------------------------------------------------------------------------
// out = LayerNorm(a + b) * g + beta, optionally also emit bf16 hi/lo split
// ---------------------------------------------------------------------------
template <int SPLIT>
__global__ __launch_bounds__(256) void add_ln_t(
    const float* __restrict__ a, const float* __restrict__ b,
    const float* __restrict__ g, const float* __restrict__ beta,
    float* __restrict__ out, __nv_bfloat16* __restrict__ hi,
    __nv_bfloat16* __restrict__ lo)
{
    const int n = blockIdx.x, tid = threadIdx.x;
    const size_t base = (size_t)n * D_;

    float v[3], s = 0.f, ss = 0.f;
#pragma unroll
    for (int t = 0; t < 3; t++) {
        int c = tid + t * 256;
        float x = a[base + c] + b[base + c];
        v[t] = x; s += x; ss += x * x;
    }
#pragma unroll
    for (int off = 16; off > 0; off >>= 1) {
        s  += __shfl_xor_sync(0xffffffffu, s,  off);
        ss += __shfl_xor_sync(0xffffffffu, ss, off);
    }
    __shared__ float sh_s[8], sh_ss[8];
    const int wid = tid >> 5, lane = tid & 31;
    if (lane == 0) { sh_s[wid] = s; sh_ss[wid] = ss; }
    __syncthreads();
    s = 0.f; ss = 0.f;
#pragma unroll
    for (int w = 0; w < 8; w++) { s += sh_s[w]; ss += sh_ss[w]; }

    const float mu  = s * (1.0f / D_);
    const float var = ss * (1.0f / D_) - mu * mu;
    const float r   = rsqrtf(var + EPSLN);
#pragma unroll
    for (int t = 0; t < 3; t++) {
        int c = tid + t * 256;
        float y = (v[t] - mu) * r * g[c] + beta[c];
        out[base + c] = y;
        if (SPLIT) {
            __nv_bfloat16 hh = __float2bfloat16(y);
            hi[base + c] = hh;
            lo[base + c] = __float2bfloat16(y - __bfloat162float(hh));
        }
    }
}

// ---------------------------------------------------------------------------
extern "C" void kernel_launch(void* const* d_in, const int* in_sizes, int n_in,
                              void* d_out, int out_size)
{
    const float* x     = (const float*)d_in[0];
    const float* w_row = (const float*)d_in[1];
    const float* b_row = (const float*)d_in[2];
    const float* w_col = (const float*)d_in[3];
    const float* b_col = (const float*)d_in[4];
    const float* g1    = (const float*)d_in[5];
    const float* beta1 = (const float*)d_in[6];
    const float* g2    = (const float*)d_in[7];
    const float* beta2 = (const float*)d_in[8];
    const int*   pmask = (const int*)d_in[9];
    float* out = (float*)d_out;

    float *qkv, *tmp;
    cudaGetSymbolAddress((void**)&qkv, g_qkv);
    cudaGetSymbolAddress((void**)&tmp, g_tmp);
    __nv_bfloat16 *ah, *al, *wrh, *wrl, *wch, *wcl;
    cudaGetSymbolAddress((void**)&ah,  g_ah);
    cudaGetSymbolAddress((void**)&al,  g_al);
    cudaGetSymbolAddress((void**)&wrh, g_wrh);
    cudaGetSymbolAddress((void**)&wrl, g_wrl);
    cudaGetSymbolAddress((void**)&wch, g_wch);
    cudaGetSymbolAddress((void**)&wcl, g_wcl);

    __nv_bfloat16* qkvh = (__nv_bfloat16*)qkv;
    __nv_bfloat16* qkvl = qkvh + (size_t)N_ * D3_;

    cudaFuncSetAttribute(gemm_hmma_x3, cudaFuncAttributeMaxDynamicSharedMemorySize, SMEM_GEMM);
    cudaFuncSetAttribute(attn_mma<2>, cudaFuncAttributeMaxDynamicSharedMemorySize, SMEM_ATT_ROW);
    cudaFuncSetAttribute(attn_mma<1>, cudaFuncAttributeMaxDynamicSharedMemorySize, SMEM_ATT_COL);

    const int nx = N_ * D_;
    const int nw = D3_ * D_;
    dim3 gemm_grid(GM / 128, N_ / 128);

    split_f32<<<nw / 1024, 256>>>(w_row, wrh, wrl, nw);
    split_f32<<<nw / 1024, 256>>>(w_col, wch, wcl, nw);
    split_f32<<<nx / 1024, 256>>>(x, ah, al, nx);

    // ---- row pass ----
    gemm_hmma_x3<<<gemm_grid, 256, SMEM_GEMM>>>(ah, al, wrh, wrl, b_row, qkvh, qkvl);
    attn_mma<2><<<dim3(H_, E_), 256, SMEM_ATT_ROW>>>(qkvh, qkvl, pmask, tmp, 0);
    add_ln_t<1><<<N_, 256>>>(x, tmp, g1, beta1, out, ah, al);

    // ---- column pass ----
    gemm_hmma_x3<<<gemm_grid, 256, SMEM_GEMM>>>(ah, al, wch, wcl, b_col, qkvh, qkvl);
    attn_mma<1><<<dim3(H_, L_), 256, SMEM_ATT_COL>>>(qkvh, qkvl, pmask, tmp, 1);
    add_ln_t<0><<<N_, 256>>>(out, tmp, g2, beta2, out, nullptr, nullptr);
}

// round 16
// speedup vs baseline: 1.5077x; 1.5077x over previous
#include <cuda_runtime.h>
#include <cuda_bf16.h>
#include <cstdint>

// Fixed problem shapes
#define B_  1
#define E_  128
#define L_  256
#define H_  12
#define DH_ 64
#define D_  768          // H_*DH_
#define D3_ 2304         // 3*D_
#define N_  32768        // B_*E_*L_
#define EPSLN 1e-5f
#define NEGV  -10000.0f

// Scratch (allocations forbidden -> device globals)
__device__ float g_qkv[(size_t)N_ * D3_];            // 302 MB; aliased as 2x bf16 [N,D3]
__device__ float g_tmp[(size_t)N_ * D_];             // 100 MB
__device__ __nv_bfloat16 g_ah[(size_t)N_ * D_];
__device__ __nv_bfloat16 g_al[(size_t)N_ * D_];
__device__ __nv_bfloat16 g_wrh[(size_t)D3_ * D_];
__device__ __nv_bfloat16 g_wrl[(size_t)D3_ * D_];
__device__ __nv_bfloat16 g_wch[(size_t)D3_ * D_];
__device__ __nv_bfloat16 g_wcl[(size_t)D3_ * D_];

// ---------------------------------------------------------------------------
// arch-agnostic PTX helpers
// ---------------------------------------------------------------------------
__device__ __forceinline__ uint32_t smem_u32(const void* p) {
    uint32_t a;
    asm("{ .reg .u64 t; cvta.to.shared.u64 t, %1; cvt.u32.u64 %0, t; }" : "=r"(a) : "l"(p));
    return a;
}
__device__ __forceinline__ void cp16(uint32_t s, const void* g) {
    asm volatile("cp.async.cg.shared.global [%0], [%1], 16;" :: "r"(s), "l"(g) : "memory");
}
__device__ __forceinline__ void cp_commit() {
    asm volatile("cp.async.commit_group;" ::: "memory");
}
template <int N>
__device__ __forceinline__ void cp_wait() {
    asm volatile("cp.async.wait_group %0;" :: "n"(N) : "memory");
}
__device__ __forceinline__ void ldsm4(uint32_t* r, uint32_t a) {
    asm volatile("ldmatrix.sync.aligned.m8n8.x4.shared.b16 {%0,%1,%2,%3}, [%4];"
                 : "=r"(r[0]), "=r"(r[1]), "=r"(r[2]), "=r"(r[3]) : "r"(a));
}
__device__ __forceinline__ void ldsm2t(uint32_t* r, uint32_t a) {
    asm volatile("ldmatrix.sync.aligned.m8n8.x2.trans.shared.b16 {%0,%1}, [%2];"
                 : "=r"(r[0]), "=r"(r[1]) : "r"(a));
}
__device__ __forceinline__ void mma16816(float* d, const uint32_t* a, const uint32_t* b) {
    asm volatile(
        "mma.sync.aligned.m16n8k16.row.col.f32.bf16.bf16.f32 "
        "{%0,%1,%2,%3}, {%4,%5,%6,%7}, {%8,%9}, {%0,%1,%2,%3};"
        : "+f"(d[0]), "+f"(d[1]), "+f"(d[2]), "+f"(d[3])
        : "r"(a[0]), "r"(a[1]), "r"(a[2]), "r"(a[3]), "r"(b[0]), "r"(b[1]));
}
__device__ __forceinline__ uint32_t pack2(__nv_bfloat16 a, __nv_bfloat16 b) {
    __nv_bfloat162 t = __halves2bfloat162(a, b);
    return *reinterpret_cast<uint32_t*>(&t);
}
__device__ __forceinline__ uint32_t sw128(uint32_t off) {
    return off ^ ((off >> 3) & 0x70);
}

// ---------------------------------------------------------------------------
// split: fp32 -> bf16 hi + bf16 lo
// ---------------------------------------------------------------------------
__global__ __launch_bounds__(256) void split_f32(
    const float* __restrict__ in, __nv_bfloat16* __restrict__ hi,
    __nv_bfloat16* __restrict__ lo, int n)
{
    int i = (blockIdx.x * 256 + threadIdx.x) * 4;
    if (i >= n) return;
    float4 v = *(const float4*)(in + i);
    float f[4] = {v.x, v.y, v.z, v.w};
    __nv_bfloat16 h[4], l[4];
#pragma unroll
    for (int q = 0; q < 4; q++) {
        h[q] = __float2bfloat16(f[q]);
        l[q] = __float2bfloat16(f[q] - __bfloat162float(h[q]));
    }
    *(__nv_bfloat162*)(hi + i)     = __halves2bfloat162(h[0], h[1]);
    *(__nv_bfloat162*)(hi + i + 2) = __halves2bfloat162(h[2], h[3]);
    *(__nv_bfloat162*)(lo + i)     = __halves2bfloat162(l[0], l[1]);
    *(__nv_bfloat162*)(lo + i + 2) = __halves2bfloat162(l[2], l[3]);
}

// ---------------------------------------------------------------------------
// bf16 3-way-split GEMM via mma.sync (R12 epilogue — best known).
// ---------------------------------------------------------------------------
#define GK 768
#define GM 2304
#define BKC 32
#define NIT 24
#define ABUF_B 16384
#define STG_B  (2 * ABUF_B)
#define SMEM_GEMM (3 * STG_B + 1024)

__device__ __forceinline__ void issue_stage3(
    uint32_t sbase, int kc,
    const __nv_bfloat16* __restrict__ pAh, const __nv_bfloat16* __restrict__ pAl,
    const __nv_bfloat16* __restrict__ pBh, const __nv_bfloat16* __restrict__ pBl,
    int tid)
{
#pragma unroll
    for (int i = 0; i < 4; i++) {
        int idx = i * 256 + tid;
        int r = idx >> 3, half = (idx >> 2) & 1, c16 = idx & 3;
        const __nv_bfloat16* g = (half ? pAl : pAh) + (size_t)r * GK + kc + c16 * 8;
        uint32_t off = (uint32_t)(r * 128 + half * 64 + c16 * 16);
        cp16(sbase + sw128(off), g);
    }
#pragma unroll
    for (int i = 0; i < 4; i++) {
        int idx = i * 256 + tid;
        int r = idx >> 3, half = (idx >> 2) & 1, c16 = idx & 3;
        const __nv_bfloat16* g = (half ? pBl : pBh) + (size_t)r * GK + kc + c16 * 8;
        uint32_t off = (uint32_t)(r * 128 + half * 64 + c16 * 16);
        cp16(sbase + ABUF_B + sw128(off), g);
    }
    cp_commit();
}

__global__ __launch_bounds__(256, 2) void gemm_hmma_x3(
    const __nv_bfloat16* __restrict__ Ah, const __nv_bfloat16* __restrict__ Al,
    const __nv_bfloat16* __restrict__ Bh, const __nv_bfloat16* __restrict__ Bl,
    const float* __restrict__ bias,
    __nv_bfloat16* __restrict__ Ch, __nv_bfloat16* __restrict__ Cl)
{
    extern __shared__ char dynsm[];
    uint32_t smb = smem_u32(dynsm);
    smb = (smb + 1023u) & ~1023u;

    const int tid  = threadIdx.x;
    const int wid  = tid >> 5, lane = tid & 31;
    const int wm   = wid >> 2;
    const int wn   = wid & 3;
    const int tileN = blockIdx.x;
    const int tileM = blockIdx.y;

    const __nv_bfloat16* pA0 = Ah + (size_t)tileM * 128 * GK;
    const __nv_bfloat16* pA1 = Al + (size_t)tileM * 128 * GK;
    const __nv_bfloat16* pB0 = Bh + (size_t)tileN * 128 * GK;
    const __nv_bfloat16* pB1 = Bl + (size_t)tileN * 128 * GK;

    issue_stage3(smb + 0 * STG_B, 0 * BKC, pA0, pA1, pB0, pB1, tid);
    issue_stage3(smb + 1 * STG_B, 1 * BKC, pA0, pA1, pB0, pB1, tid);

    float acc[4][4][4];
#pragma unroll
    for (int a = 0; a < 4; a++)
#pragma unroll
        for (int b = 0; b < 4; b++)
#pragma unroll
            for (int c = 0; c < 4; c++) acc[a][b][c] = 0.f;

    const int aRow  = lane & 15;
    const int aColB = (lane >> 4) * 16;
    const int grp   = lane >> 3;
    const int bRow  = ((grp >> 1) * 8) + (lane & 7);
    const int bColB = (grp & 1) * 16;

    int st = 0;
    for (int it = 0; it < NIT; it++) {
        if (it < NIT - 2) cp_wait<1>(); else cp_wait<0>();
        __syncthreads();

        if (it + 2 < NIT) {
            int stn = st + 2; if (stn >= 3) stn -= 3;
            issue_stage3(smb + (uint32_t)stn * STG_B, (it + 2) * BKC,
                         pA0, pA1, pB0, pB1, tid);
        }

        const uint32_t sA = smb + (uint32_t)st * STG_B;
        const uint32_t sB = sA + ABUF_B;

#pragma unroll
        for (int ks = 0; ks < 2; ks++) {
            const int kb = ks * 32;
            uint32_t ah[4][4], al4[4][4], bh4[2][4], bl4[2][4];
#pragma unroll
            for (int mt = 0; mt < 4; mt++) {
                uint32_t off = (uint32_t)((wm * 64 + mt * 16 + aRow) * 128 + kb + aColB);
                ldsm4(ah[mt],  sA + sw128(off));
                ldsm4(al4[mt], sA + sw128(off + 64));
            }
#pragma unroll
            for (int pr = 0; pr < 2; pr++) {
                uint32_t off = (uint32_t)((wn * 32 + pr * 16 + bRow) * 128 + kb + bColB);
                ldsm4(bh4[pr], sB + sw128(off));
                ldsm4(bl4[pr], sB + sw128(off + 64));
            }
#pragma unroll
            for (int mt = 0; mt < 4; mt++)
#pragma unroll
                for (int pr = 0; pr < 2; pr++)
#pragma unroll
                    for (int half = 0; half < 2; half++) {
                        const int nt = pr * 2 + half;
                        mma16816(acc[mt][nt], ah[mt],  &bh4[pr][half * 2]);
                        mma16816(acc[mt][nt], ah[mt],  &bl4[pr][half * 2]);
                        mma16816(acc[mt][nt], al4[mt], &bh4[pr][half * 2]);
                    }
        }
        st++; if (st == 3) st = 0;
    }

    const int r0 = tileM * 128 + wm * 64 + (lane >> 2);
    const int c0 = tileN * 128 + wn * 32 + (lane & 3) * 2;
#pragma unroll
    for (int mt = 0; mt < 4; mt++) {
#pragma unroll
        for (int nt = 0; nt < 4; nt++) {
            const int row = r0 + mt * 16;
            const int col = c0 + nt * 8;
            const float b0 = bias[col], b1 = bias[col + 1];
#pragma unroll
            for (int rr = 0; rr < 2; rr++) {
                float y0 = acc[mt][nt][rr * 2 + 0] + b0;
                float y1 = acc[mt][nt][rr * 2 + 1] + b1;
                __nv_bfloat16 h0 = __float2bfloat16(y0);
                __nv_bfloat16 h1 = __float2bfloat16(y1);
                __nv_bfloat16 l0 = __float2bfloat16(y0 - __bfloat162float(h0));
                __nv_bfloat16 l1 = __float2bfloat16(y1 - __bfloat162float(h1));
                size_t p = (size_t)(row + rr * 8) * GM + col;
                *(__nv_bfloat162*)(Ch + p) = __halves2bfloat162(h0, h1);
                *(__nv_bfloat162*)(Cl + p) = __halves2bfloat162(l0, l1);
            }
        }
    }
}

// ---------------------------------------------------------------------------
// Flash-style HMMA attention, bf16 hi/lo qkv inputs.
//   row pass: MT=2, NST=3 stages, 1 CTA/SM  — grid (12, 128), base=e*256, step=1
//   col pass: MT=1, NST=2 stages, 2 CTAs/SM — grid (12, 256), base=l,     step=256
// ---------------------------------------------------------------------------
#define CH_TILE 8192
#define CH_STG  (4 * CH_TILE)

template <int MT, int NST, int MINC>
__global__ __launch_bounds__(256, MINC) void attn_mma(
    const __nv_bfloat16* __restrict__ qh, const __nv_bfloat16* __restrict__ ql,
    const int* __restrict__ mask, float* __restrict__ out, int colmode)
{
    constexpr int NQ  = MT * 128;
    constexpr int NCH = MT * 2;
    extern __shared__ __align__(128) char smraw[];
    const uint32_t uQh = smem_u32(smraw);
    const uint32_t uQl = uQh + NQ * 128;
    const uint32_t uST = uQl + NQ * 128;
    float* negs = (float*)(smraw + 2 * NQ * 128 + NST * CH_STG);

    const int tid  = threadIdx.x;
    const int wid  = tid >> 5, lane = tid & 31;
    const int h    = blockIdx.x;
    const int base = colmode ? (int)blockIdx.y : (int)blockIdx.y * 256;
    const int step = colmode ? 256 : 1;

#pragma unroll
    for (int i = 0; i < NQ / 16; i++) {
        int idx = i * 256 + tid;
        int t = (idx >= NQ * 8);
        int r = (idx >> 3) & (NQ - 1);
        int c = idx & 7;
        const __nv_bfloat16* src = (t ? ql : qh) + (size_t)(base + r * step) * D3_ + h * 64 + c * 8;
        cp16((t ? uQl : uQh) + sw128((uint32_t)(r * 128 + c * 16)), src);
    }
    cp_commit();
    for (int i = tid; i < NQ; i += 256)
        negs[i] = mask[base + i * step] ? NEGV : 0.f;

    auto issue_ch = [&](int ch) {
        uint32_t sb = uST + (uint32_t)(ch % NST) * CH_STG;
#pragma unroll
        for (int i = 0; i < 8; i++) {
            int idx = i * 256 + tid;
            int tile = idx >> 9;
            int r = (idx >> 3) & 63;
            int c = idx & 7;
            const __nv_bfloat16* bp = (tile & 1) ? ql : qh;
            int coff = (tile >= 2) ? 1536 : 768;
            const __nv_bfloat16* src = bp + (size_t)(base + (ch * 64 + r) * step) * D3_
                                       + coff + h * 64 + c * 8;
            cp16(sb + (uint32_t)tile * CH_TILE + sw128((uint32_t)(r * 128 + c * 16)), src);
        }
        cp_commit();
    };
    issue_ch(0);
    if (NCH > 1) issue_ch(1);

    float s[MT][8][4], o[MT][8][4], mrow[MT][2], lrow[MT][2];
#pragma unroll
    for (int mt = 0; mt < MT; mt++) {
        mrow[mt][0] = mrow[mt][1] = -1e30f;
        lrow[mt][0] = lrow[mt][1] = 0.f;
#pragma unroll
        for (int nt = 0; nt < 8; nt++)
#pragma unroll
            for (int c = 0; c < 4; c++) o[mt][nt][c] = 0.f;
    }

    const int aRow  = lane & 15;
    const int aColB = (lane >> 4) * 16;
    const int grp   = lane >> 3;
    const int bRow4 = ((grp >> 1) * 8) + (lane & 7);
    const int bColB4 = (grp & 1) * 16;

    for (int ch = 0; ch < NCH; ch++) {
        if (ch < NCH - 1) cp_wait<1>(); else cp_wait<0>();
        __syncthreads();
        if (ch + 2 < NCH) issue_ch(ch + 2);

        const uint32_t sK = uST + (uint32_t)(ch % NST) * CH_STG;

#pragma unroll
        for (int mt = 0; mt < MT; mt++)
#pragma unroll
            for (int nt = 0; nt < 8; nt++)
#pragma unroll
                for (int c = 0; c < 4; c++) s[mt][nt][c] = 0.f;

#pragma unroll
        for (int kq = 0; kq < 4; kq++) {
            uint32_t ah[MT][4], al[MT][4];
#pragma unroll
            for (int mt = 0; mt < MT; mt++) {
                uint32_t off = (uint32_t)((wid * (MT * 16) + mt * 16 + aRow) * 128
                                          + kq * 32 + aColB);
                ldsm4(ah[mt], uQh + sw128(off));
                ldsm4(al[mt], uQl + sw128(off));
            }
            uint32_t kh4[4][4], kl4[4][4];
#pragma unroll
            for (int pr = 0; pr < 4; pr++) {
                uint32_t off = (uint32_t)((pr * 16 + bRow4) * 128 + kq * 32 + bColB4);
                ldsm4(kh4[pr], sK + sw128(off));
                ldsm4(kl4[pr], sK + CH_TILE + sw128(off));
            }
#pragma unroll
            for (int mt = 0; mt < MT; mt++)
#pragma unroll
                for (int pr = 0; pr < 4; pr++)
#pragma unroll
                    for (int half = 0; half < 2; half++) {
                        const int nt = pr * 2 + half;
                        mma16816(s[mt][nt], ah[mt], &kh4[pr][half * 2]);
                        mma16816(s[mt][nt], ah[mt], &kl4[pr][half * 2]);
                        mma16816(s[mt][nt], al[mt], &kh4[pr][half * 2]);
                    }
        }

#pragma unroll
        for (int nt = 0; nt < 8; nt++) {
            int j = ch * 64 + nt * 8 + (lane & 3) * 2;
            float n0 = negs[j], n1 = negs[j + 1];
#pragma unroll
            for (int mt = 0; mt < MT; mt++) {
                s[mt][nt][0] = s[mt][nt][0] * 0.125f + n0;
                s[mt][nt][1] = s[mt][nt][1] * 0.125f + n1;
                s[mt][nt][2] = s[mt][nt][2] * 0.125f + n0;
                s[mt][nt][3] = s[mt][nt][3] * 0.125f + n1;
            }
        }
#pragma unroll
        for (int mt = 0; mt < MT; mt++) {
#pragma unroll
            for (int hf = 0; hf < 2; hf++) {
                float rm = -1e30f;
#pragma unroll
                for (int nt = 0; nt < 8; nt++)
                    rm = fmaxf(rm, fmaxf(s[mt][nt][2 * hf], s[mt][nt][2 * hf + 1]));
                rm = fmaxf(rm, __shfl_xor_sync(0xffffffffu, rm, 1));
                rm = fmaxf(rm, __shfl_xor_sync(0xffffffffu, rm, 2));
                float mo = mrow[mt][hf];
                float mn = fmaxf(mo, rm);
                float corr = __expf(mo - mn);
                float rs = 0.f;
#pragma unroll
                for (int nt = 0; nt < 8; nt++) {
                    float p0 = __expf(s[mt][nt][2 * hf]     - mn);
                    float p1 = __expf(s[mt][nt][2 * hf + 1] - mn);
                    s[mt][nt][2 * hf] = p0; s[mt][nt][2 * hf + 1] = p1;
                    rs += p0 + p1;
                    o[mt][nt][2 * hf] *= corr; o[mt][nt][2 * hf + 1] *= corr;
                }
                rs += __shfl_xor_sync(0xffffffffu, rs, 1);
                rs += __shfl_xor_sync(0xffffffffu, rs, 2);
                lrow[mt][hf] = lrow[mt][hf] * corr + rs;
                mrow[mt][hf] = mn;
            }
        }

#pragma unroll
        for (int kk = 0; kk < 4; kk++) {
            uint32_t pah[MT][4], pal[MT][4];
#pragma unroll
            for (int mt = 0; mt < MT; mt++) {
#pragma unroll
                for (int q = 0; q < 4; q++) {
                    int nt = kk * 2 + (q >> 1);
                    int i0 = (q & 1) * 2;
                    float p0 = s[mt][nt][i0], p1 = s[mt][nt][i0 + 1];
                    __nv_bfloat16 h0 = __float2bfloat16(p0);
                    __nv_bfloat16 h1 = __float2bfloat16(p1);
                    pah[mt][q] = pack2(h0, h1);
                    __nv_bfloat16 l0 = __float2bfloat16(p0 - __bfloat162float(h0));
                    __nv_bfloat16 l1 = __float2bfloat16(p1 - __bfloat162float(h1));
                    pal[mt][q] = pack2(l0, l1);
                }
            }
#pragma unroll
            for (int nt = 0; nt < 8; nt++) {
                uint32_t vbh[2], vbl[2];
                uint32_t voff = sw128((uint32_t)((kk * 16 + (lane & 15)) * 128 + nt * 16));
                ldsm2t(vbh, sK + 2 * CH_TILE + voff);
                ldsm2t(vbl, sK + 3 * CH_TILE + voff);
#pragma unroll
                for (int mt = 0; mt < MT; mt++) {
                    mma16816(o[mt][nt], pah[mt], vbh);
                    mma16816(o[mt][nt], pah[mt], vbl);
                    mma16816(o[mt][nt], pal[mt], vbh);
                }
            }
        }
    }

#pragma unroll
    for (int mt = 0; mt < MT; mt++) {
#pragma unroll
        for (int hf = 0; hf < 2; hf++) {
            float inv = 1.f / lrow[mt][hf];
            int qrow = wid * (MT * 16) + mt * 16 + hf * 8 + (lane >> 2);
            size_t ob = (size_t)(base + qrow * step) * D_ + h * 64 + (lane & 3) * 2;
#pragma unroll
            for (int nt = 0; nt < 8; nt++) {
                float2 v = {o[mt][nt][2 * hf] * inv, o[mt][nt][2 * hf + 1] * inv};
                *(float2*)(out + ob + nt * 8) = v;
            }
        }
    }
}

#define SMEM_ATT_ROW (2 * 256 * 128 + 3 * CH_STG + 256 * 4)   // ~164 KB, 1 CTA/SM
#define SMEM_ATT_COL (2 * 128 * 128 + 2 * CH_STG + 128 * 4)   // ~97 KB, 2 CTAs/SM

// ---------------------------------------------------------------------------
// out = LayerNorm(a + b) * g + beta, optionally also emit bf16 hi/lo split
// ---------------------------------------------------------------------------
template <int SPLIT>
__global__ __launch_bounds__(256) void add_ln_t(
    const float* __restrict__ a, const float* __restrict__ b,
    const float* __restrict__ g, const float* __restrict__ beta,
    float* __restrict__ out, __nv_bfloat16* __restrict__ hi,
    __nv_bfloat16* __restrict__ lo)
{
    const int n = blockIdx.x, tid = threadIdx.x;
    const size_t base = (size_t)n * D_;

    float v[3], s = 0.f, ss = 0.f;
#pragma unroll
    for (int t = 0; t < 3; t++) {
        int c = tid + t * 256;
        float x = a[base + c] + b[base + c];
        v[t] = x; s += x; ss += x * x;
    }
#pragma unroll
    for (int off = 16; off > 0; off >>= 1) {
        s  += __shfl_xor_sync(0xffffffffu, s,  off);
        ss += __shfl_xor_sync(0xffffffffu, ss, off);
    }
    __shared__ float sh_s[8], sh_ss[8];
    const int wid = tid >> 5, lane = tid & 31;
    if (lane == 0) { sh_s[wid] = s; sh_ss[wid] = ss; }
    __syncthreads();
    s = 0.f; ss = 0.f;
#pragma unroll
    for (int w = 0; w < 8; w++) { s += sh_s[w]; ss += sh_ss[w]; }

    const float mu  = s * (1.0f / D_);
    const float var = ss * (1.0f / D_) - mu * mu;
    const float r   = rsqrtf(var + EPSLN);
#pragma unroll
    for (int t = 0; t < 3; t++) {
        int c = tid + t * 256;
        float y = (v[t] - mu) * r * g[c] + beta[c];
        out[base + c] = y;
        if (SPLIT) {
            __nv_bfloat16 hh = __float2bfloat16(y);
            hi[base + c] = hh;
            lo[base + c] = __float2bfloat16(y - __bfloat162float(hh));
        }
    }
}

// ---------------------------------------------------------------------------
extern "C" void kernel_launch(void* const* d_in, const int* in_sizes, int n_in,
                              void* d_out, int out_size)
{
    const float* x     = (const float*)d_in[0];
    const float* w_row = (const float*)d_in[1];
    const float* b_row = (const float*)d_in[2];
    const float* w_col = (const float*)d_in[3];
    const float* b_col = (const float*)d_in[4];
    const float* g1    = (const float*)d_in[5];
    const float* beta1 = (const float*)d_in[6];
    const float* g2    = (const float*)d_in[7];
    const float* beta2 = (const float*)d_in[8];
    const int*   pmask = (const int*)d_in[9];
    float* out = (float*)d_out;

    float *qkv, *tmp;
    cudaGetSymbolAddress((void**)&qkv, g_qkv);
    cudaGetSymbolAddress((void**)&tmp, g_tmp);
    __nv_bfloat16 *ah, *al, *wrh, *wrl, *wch, *wcl;
    cudaGetSymbolAddress((void**)&ah,  g_ah);
    cudaGetSymbolAddress((void**)&al,  g_al);
    cudaGetSymbolAddress((void**)&wrh, g_wrh);
    cudaGetSymbolAddress((void**)&wrl, g_wrl);
    cudaGetSymbolAddress((void**)&wch, g_wch);
    cudaGetSymbolAddress((void**)&wcl, g_wcl);

    __nv_bfloat16* qkvh = (__nv_bfloat16*)qkv;
    __nv_bfloat16* qkvl = qkvh + (size_t)N_ * D3_;

    cudaFuncSetAttribute(gemm_hmma_x3, cudaFuncAttributeMaxDynamicSharedMemorySize, SMEM_GEMM);
    cudaFuncSetAttribute((attn_mma<2, 3, 1>), cudaFuncAttributeMaxDynamicSharedMemorySize, SMEM_ATT_ROW);
    cudaFuncSetAttribute((attn_mma<1, 2, 2>), cudaFuncAttributeMaxDynamicSharedMemorySize, SMEM_ATT_COL);

    const int nx = N_ * D_;
    const int nw = D3_ * D_;
    dim3 gemm_grid(GM / 128, N_ / 128);

    split_f32<<<nw / 1024, 256>>>(w_row, wrh, wrl, nw);
    split_f32<<<nw / 1024, 256>>>(w_col, wch, wcl, nw);
    split_f32<<<nx / 1024, 256>>>(x, ah, al, nx);

    // ---- row pass ----
    gemm_hmma_x3<<<gemm_grid, 256, SMEM_GEMM>>>(ah, al, wrh, wrl, b_row, qkvh, qkvl);
    attn_mma<2, 3, 1><<<dim3(H_, E_), 256, SMEM_ATT_ROW>>>(qkvh, qkvl, pmask, tmp, 0);
    add_ln_t<1><<<N_, 256>>>(x, tmp, g1, beta1, out, ah, al);

    // ---- column pass ----
    gemm_hmma_x3<<<gemm_grid, 256, SMEM_GEMM>>>(ah, al, wch, wcl, b_col, qkvh, qkvl);
    attn_mma<1, 2, 2><<<dim3(H_, L_), 256, SMEM_ATT_COL>>>(qkvh, qkvl, pmask, tmp, 1);
    add_ln_t<0><<<N_, 256>>>(out, tmp, g2, beta2, out, nullptr, nullptr);
}